// round 13
// baseline (speedup 1.0000x reference)
#include <cuda_runtime.h>
#include <cuda_fp16.h>

#define H      256
#define TXT    768
#define BIO    32
#define TM     128
#define NTHR   512
#define EPSLN  1e-5f
#define PRC    2

#define LDA3   520      // A3 smem pitch (half elems)
#define LDT    40       // K-tile smem pitch (half elems)

// ---------------- device scratch ----------------
__device__ float g_M [H * H];
__device__ float g_c [H];
__device__ float g_Ag[H * H];
__device__ float g_Bg[H * H];
__device__ float g_uA[H];
__device__ float g_uB[H];
__device__ float g_e [H];

__device__ __align__(16) __half g_W1h[H * BIO];
__device__ __align__(16) __half g_W2h[H * TXT];
__device__ __align__(16) __half g_W3h[H * 512];

// ---------------- precompute 1 ----------------
__global__ void precompute1(const float* __restrict__ in_proj_w,
                            const float* __restrict__ in_proj_b,
                            const float* __restrict__ out_w,
                            const float* __restrict__ out_b) {
    __shared__ float s_row[PRC][H];
    __shared__ float s_part[8][PRC];
    const int i0 = blockIdx.x * PRC;
    const int j  = threadIdx.x;
    const int lane = j & 31, wrp = j >> 5;
#pragma unroll
    for (int r = 0; r < PRC; r++) s_row[r][j] = out_w[(i0 + r) * H + j];
    __syncthreads();
    float acc[PRC];
#pragma unroll
    for (int r = 0; r < PRC; r++) acc[r] = 0.f;
#pragma unroll 8
    for (int k = 0; k < H; k++) {
        float w = in_proj_w[(2 * H + k) * H + j];
#pragma unroll
        for (int r = 0; r < PRC; r++) acc[r] = fmaf(s_row[r][k], w, acc[r]);
    }
#pragma unroll
    for (int r = 0; r < PRC; r++) g_M[(i0 + r) * H + j] = acc[r];
    float bv = in_proj_b[2 * H + j];
#pragma unroll
    for (int r = 0; r < PRC; r++) {
        float v = s_row[r][j] * bv;
#pragma unroll
        for (int off = 16; off; off >>= 1) v += __shfl_xor_sync(0xffffffffu, v, off);
        if (lane == 0) s_part[wrp][r] = v;
    }
    __syncthreads();
    if (j < PRC) {
        float s = 0.f;
#pragma unroll
        for (int w = 0; w < 8; w++) s += s_part[w][j];
        g_c[i0 + j] = s + out_b[i0 + j];
    }
}

// ---------------- precompute 2 ----------------
__global__ void precompute2(const float* __restrict__ cls1_w,
                            const float* __restrict__ cls1_b,
                            const float* __restrict__ ln_text_g,
                            const float* __restrict__ ln_text_b,
                            const float* __restrict__ ln_bio_g,
                            const float* __restrict__ ln_bio_b) {
    __shared__ float s_l[PRC][H], s_r[PRC][H];
    __shared__ float s_part[8][3 * PRC];
    const int i0 = blockIdx.x * PRC;
    const int j  = threadIdx.x;
    const int lane = j & 31, wrp = j >> 5;
#pragma unroll
    for (int r = 0; r < PRC; r++) {
        s_l[r][j] = cls1_w[(i0 + r) * 2 * H + j];
        s_r[r][j] = cls1_w[(i0 + r) * 2 * H + H + j];
    }
    __syncthreads();
    float a[PRC], b[PRC];
#pragma unroll
    for (int r = 0; r < PRC; r++) { a[r] = 0.f; b[r] = 0.f; }
#pragma unroll 8
    for (int k = 0; k < H; k++) {
        float m = g_M[k * H + j];
#pragma unroll
        for (int r = 0; r < PRC; r++) {
            a[r] = fmaf(s_l[r][k], m, a[r]);
            b[r] = fmaf(s_r[r][k], m, b[r]);
        }
    }
    float gt = ln_text_g[j], gb = ln_bio_g[j];
    float lt = ln_text_b[j], lb = ln_bio_b[j];
    float cc = g_c[j];
    float vals[3 * PRC];
#pragma unroll
    for (int r = 0; r < PRC; r++) {
        float ag = a[r] * gt, bg = b[r] * gb;
        g_Ag[(i0 + r) * H + j] = ag;
        g_Bg[(i0 + r) * H + j] = bg;
        vals[r]           = ag;
        vals[PRC + r]     = bg;
        vals[2 * PRC + r] = a[r] * lt + b[r] * lb + (s_l[r][j] + s_r[r][j]) * cc;
    }
#pragma unroll
    for (int q = 0; q < 3 * PRC; q++) {
        float v = vals[q];
#pragma unroll
        for (int off = 16; off; off >>= 1) v += __shfl_xor_sync(0xffffffffu, v, off);
        if (lane == 0) s_part[wrp][q] = v;
    }
    __syncthreads();
    if (j < 3 * PRC) {
        float s = 0.f;
#pragma unroll
        for (int w = 0; w < 8; w++) s += s_part[w][j];
        int q = j / PRC, r = j % PRC;
        if (q == 0) g_uA[i0 + r] = s;
        else if (q == 1) g_uB[i0 + r] = s;
        else g_e[i0 + r] = s + cls1_b[i0 + r];
    }
}

// ---------------- precompute 3: fp16 weight casts ----------------
__global__ void convert_weights(const float* __restrict__ bio_w,
                                const float* __restrict__ text_w) {
    int i = blockIdx.x * 256 + threadIdx.x;
    if (i < H * BIO)  g_W1h[i] = __float2half_rn(bio_w[i]);
    if (i < H * 512) {
        int n = i >> 9, k = i & 511;
        float v = (k < H) ? g_Ag[n * H + k] : g_Bg[n * H + (k - H)];
        g_W3h[i] = __float2half_rn(v);
    }
    if (i < H * TXT)  g_W2h[i] = __float2half_rn(text_w[i]);
}

// ---------------- mma helpers ----------------
__device__ __forceinline__ unsigned s2u(const void* p) {
    return (unsigned)__cvta_generic_to_shared(p);
}
__device__ __forceinline__ void ldsm4(unsigned* r, unsigned a) {
    asm volatile("ldmatrix.sync.aligned.m8n8.x4.shared.b16 {%0,%1,%2,%3}, [%4];"
                 : "=r"(r[0]), "=r"(r[1]), "=r"(r[2]), "=r"(r[3]) : "r"(a));
}
__device__ __forceinline__ void mma16816(float* d, const unsigned* a, const unsigned* b) {
    asm volatile("mma.sync.aligned.m16n8k16.row.col.f32.f16.f16.f32 "
                 "{%0,%1,%2,%3}, {%4,%5,%6,%7}, {%8,%9}, {%0,%1,%2,%3};"
                 : "+f"(d[0]), "+f"(d[1]), "+f"(d[2]), "+f"(d[3])
                 : "r"(a[0]), "r"(a[1]), "r"(a[2]), "r"(a[3]), "r"(b[0]), "r"(b[1]));
}
// one k16 step; warp tile M32xN64; single fp16 product
__device__ __forceinline__ void kstep2(unsigned aH, int aMT, unsigned bH,
                                       float (&acc)[2][8][4]) {
    unsigned ah[2][4];
    ldsm4(ah[0], aH);
    ldsm4(ah[1], aH + aMT);
#pragma unroll
    for (int p = 0; p < 4; p++) {
        unsigned bh[4];
        ldsm4(bh, bH + p * (16 * LDT * 2));
#pragma unroll
        for (int mt = 0; mt < 2; mt++) {
            mma16816(acc[mt][2 * p],     ah[mt], bh);
            mma16816(acc[mt][2 * p + 1], ah[mt], bh + 2);
        }
    }
}

// ---------------- staging (register prefetch, 512 threads) ----------------
struct WPref { uint4 h[2]; };
__device__ __forceinline__ void ldg_w(WPref& p, const __half* srcH,
                                      int rowBytes, int k0, int tid) {
#pragma unroll
    for (int u = 0; u < 2; u++) {
        int qd = tid + u * NTHR, n = qd >> 2, c = qd & 3;
        p.h[u] = *(const uint4*)((const char*)srcH + n * rowBytes + k0 * 2 + c * 16);
    }
}
__device__ __forceinline__ void sts_w(const WPref& p, __half* Bh, int tid) {
#pragma unroll
    for (int u = 0; u < 2; u++) {
        int qd = tid + u * NTHR, n = qd >> 2, c = qd & 3;
        *(uint4*)((char*)Bh + n * 80 + c * 16) = p.h[u];
    }
}
struct TPref { float4 v[2]; };
__device__ __forceinline__ void ldg_t(TPref& p, const float* text, int row0,
                                      int k0, int tid) {
#pragma unroll
    for (int u = 0; u < 2; u++) {
        int qd = tid + u * NTHR, r = qd >> 3, kq = qd & 7;
        p.v[u] = *(const float4*)&text[(row0 + r) * TXT + k0 + kq * 4];
    }
}
__device__ __forceinline__ void sts_t(const TPref& p, __half* A2h, int tid) {
#pragma unroll
    for (int u = 0; u < 2; u++) {
        int qd = tid + u * NTHR, r = qd >> 3, kq = qd & 7;
        float vv[4] = {p.v[u].x, p.v[u].y, p.v[u].z, p.v[u].w};
#pragma unroll
        for (int i = 0; i < 4; i++)
            A2h[r * LDT + kq * 4 + i] = __float2half_rn(vv[i]);
    }
}

// ---------------- smem layout (byte offsets) ----------------
#define OFF_A3H 0            // 128 x 520 halves = 133120
#define OFF_BH  133120       // 2 bufs x 20480
#define BUF_WB  20480
#define OFF_A2H 174080       // 2 bufs x 10240
#define BUF_AB  10240
#define OFF_VEC 194560       // 2304 floats
#define OFF_SS  203776       // 512 floats
#define OFF_SQ  205824       // 512 floats
#define OFF_AT  207872       // 128 floats
#define OFF_AB2 208384       // 128 floats
#define OFF_HD  208896       // 1024 floats
#define SMEM_BYTES 212992

#define V_TB 0
#define V_BB 256
#define V_UA 512
#define V_UB 768
#define V_E  1024
#define V_CG 1280
#define V_CB 1536
#define V_C2 1792

// bias add + LN + fp16 writeback into A3 (M32 warp tile: 4 stat rows/lane-quad)
__device__ __forceinline__ void ln_writeback(
    float (&acc)[2][8][4], const float* bias, float* statS, float* statQ,
    __half* A3h, int colBase, float* alpha, int wm, int wn, int lane) {
    const int q = lane & 3, rq = lane >> 2;
    const int cb0 = wn * 64 + 2 * q;
#pragma unroll
    for (int mt = 0; mt < 2; mt++)
#pragma unroll
        for (int nt = 0; nt < 8; nt++) {
            int c = cb0 + nt * 8;
            float b0 = bias[c], b1 = bias[c + 1];
            acc[mt][nt][0] += b0; acc[mt][nt][1] += b1;
            acc[mt][nt][2] += b0; acc[mt][nt][3] += b1;
        }
    float s4[4], q4[4];
#pragma unroll
    for (int mt = 0; mt < 2; mt++) {
        float s0 = 0, q0 = 0, s1 = 0, q1 = 0;
#pragma unroll
        for (int nt = 0; nt < 8; nt++) {
            s0 += acc[mt][nt][0] + acc[mt][nt][1];
            s1 += acc[mt][nt][2] + acc[mt][nt][3];
            q0 = fmaf(acc[mt][nt][0], acc[mt][nt][0], fmaf(acc[mt][nt][1], acc[mt][nt][1], q0));
            q1 = fmaf(acc[mt][nt][2], acc[mt][nt][2], fmaf(acc[mt][nt][3], acc[mt][nt][3], q1));
        }
        s4[mt * 2] = s0; q4[mt * 2] = q0; s4[mt * 2 + 1] = s1; q4[mt * 2 + 1] = q1;
    }
#pragma unroll
    for (int o = 1; o <= 2; o <<= 1)
#pragma unroll
        for (int i = 0; i < 4; i++) {
            s4[i] += __shfl_xor_sync(0xffffffffu, s4[i], o);
            q4[i] += __shfl_xor_sync(0xffffffffu, q4[i], o);
        }
    if (q == 0) {
#pragma unroll
        for (int i = 0; i < 4; i++) {
            int r = wm * 32 + (i >> 1) * 16 + rq + (i & 1) * 8;
            statS[wn * 128 + r] = s4[i];
            statQ[wn * 128 + r] = q4[i];
        }
    }
    __syncthreads();
    float inv[4];
#pragma unroll
    for (int i = 0; i < 4; i++) {
        int r = wm * 32 + (i >> 1) * 16 + rq + (i & 1) * 8;
        float S = statS[r] + statS[128 + r] + statS[256 + r] + statS[384 + r];
        float Q = statQ[r] + statQ[128 + r] + statQ[256 + r] + statQ[384 + r];
        float m = S * (1.f / H);
        float iv = rsqrtf(fmaf(Q, 1.f / H, -m * m) + EPSLN);
        inv[i] = iv;
        if (q == 0 && wn == 0) alpha[r] = -iv * m;
    }
#pragma unroll
    for (int mt = 0; mt < 2; mt++)
#pragma unroll
        for (int nt = 0; nt < 8; nt++) {
            int c = colBase + cb0 + nt * 8;
#pragma unroll
            for (int h = 0; h < 2; h++) {
                int r = wm * 32 + mt * 16 + rq + h * 8;
                float iv = inv[mt * 2 + h];
                A3h[r * LDA3 + c]     = __float2half_rn(acc[mt][nt][2 * h]     * iv);
                A3h[r * LDA3 + c + 1] = __float2half_rn(acc[mt][nt][2 * h + 1] * iv);
            }
        }
}

// ---------------- main fused kernel ----------------
__global__ __launch_bounds__(NTHR, 1)
void fused_main(const float* __restrict__ bio,
                const float* __restrict__ text,
                const float* __restrict__ bio_b,
                const float* __restrict__ text_b,
                const float* __restrict__ cls_ln_g,
                const float* __restrict__ cls_ln_b,
                const float* __restrict__ cls2_w,
                const float* __restrict__ cls2_b,
                float* __restrict__ out) {
    extern __shared__ char sm[];
    __half* A3h = (__half*)(sm + OFF_A3H);
    __half* Bh  = (__half*)(sm + OFF_BH);
    __half* A2h = (__half*)(sm + OFF_A2H);
    float* vec   = (float*)(sm + OFF_VEC);
    float* statS = (float*)(sm + OFF_SS);
    float* statQ = (float*)(sm + OFF_SQ);
    float* s_at  = (float*)(sm + OFF_AT);
    float* s_ab  = (float*)(sm + OFF_AB2);
    float* s_hd  = (float*)(sm + OFF_HD);

    const int tid  = threadIdx.x;
    const int lane = tid & 31, wid = tid >> 5;
    const int wm = wid >> 2;          // 0..3 (M32 groups)
    const int wn = wid & 3;           // 0..3 (N64 groups)
    const int row0 = blockIdx.x * TM;

    const int aRowL = lane & 15;
    const int aKoff = (lane >> 4) << 3;
    const int bNoff = ((lane >> 4) << 3) + (lane & 7);
    const int bKoff = ((lane >> 3) & 1) << 3;

    const float c2b0 = cls2_b[0];
    const float c2b1 = cls2_b[1];

    const unsigned uA3h = s2u(A3h) + ((wm * 32 + aRowL) * LDA3 + aKoff) * 2;
    const unsigned uA2h = s2u(A2h) + ((wm * 32 + aRowL) * LDT + aKoff) * 2;
    const unsigned uBh  = s2u(Bh)  + ((wn * 64 + bNoff) * LDT + bKoff) * 2;
    const int aMT2 = 16 * LDT * 2;
    const int aMT3 = 16 * LDA3 * 2;

    // ---- phase 0: vectors + bio (buf1) + W1 (buf1) ----
    if (tid < 256) {
        vec[V_TB + tid] = text_b[tid];
        vec[V_BB + tid] = bio_b[tid];
        vec[V_UA + tid] = g_uA[tid];
        vec[V_UB + tid] = g_uB[tid];
        vec[V_E  + tid] = g_e[tid];
        vec[V_CG + tid] = cls_ln_g[tid];
        vec[V_CB + tid] = cls_ln_b[tid];
        vec[V_C2 + tid]       = cls2_w[tid];
        vec[V_C2 + 256 + tid] = cls2_w[256 + tid];
    }
    {
        __half* A2h1 = (__half*)((char*)A2h + BUF_AB);
#pragma unroll
        for (int u = 0; u < 2; u++) {
            int qd = tid + u * NTHR;
            int r = qd >> 3, kq = qd & 7;
            float4 v = *(const float4*)&bio[(row0 + r) * BIO + kq * 4];
            float vv[4] = {v.x, v.y, v.z, v.w};
#pragma unroll
            for (int i = 0; i < 4; i++)
                A2h1[r * LDT + kq * 4 + i] = __float2half_rn(vv[i]);
        }
        char* Bh1 = (char*)Bh + BUF_WB;
#pragma unroll
        for (int u = 0; u < 2; u++) {
            int qd = tid + u * NTHR;
            int n = qd >> 2, c = qd & 3;
            *(uint4*)(Bh1 + n * 80 + c * 16) = *(const uint4*)((const char*)g_W1h + n * 64 + c * 16);
        }
    }
    __syncthreads();

    // prefetch W2 tile0 + text tile0 (hidden under phase-1 compute)
    WPref pw;  TPref pt;
    ldg_w(pw, g_W2h, TXT * 2, 0, tid);
    ldg_t(pt, text, row0, 0, tid);

    float acc[2][8][4];

    // ---- phase 1: bio GEMM (K=32) on buf1 ----
#pragma unroll
    for (int mt = 0; mt < 2; mt++)
#pragma unroll
        for (int nt = 0; nt < 8; nt++)
#pragma unroll
            for (int j = 0; j < 4; j++) acc[mt][nt][j] = 0.f;
    kstep2(uA2h + BUF_AB,      aMT2, uBh + BUF_WB,      acc);
    kstep2(uA2h + BUF_AB + 32, aMT2, uBh + BUF_WB + 32, acc);
    ln_writeback(acc, vec + V_BB, statS, statQ, A3h, 256, s_ab, wm, wn, lane);

    // ---- phase 2: text GEMM (K=768, 24 tiles, smem double-buffer) ----
#pragma unroll
    for (int mt = 0; mt < 2; mt++)
#pragma unroll
        for (int nt = 0; nt < 8; nt++)
#pragma unroll
            for (int j = 0; j < 4; j++) acc[mt][nt][j] = 0.f;

    for (int kt = 0; kt < 24; kt++) {
        const int wb = (kt & 1) * BUF_WB;
        const int ab = (kt & 1) * BUF_AB;
        sts_w(pw, (__half*)((char*)Bh + wb), tid);
        sts_t(pt, (__half*)((char*)A2h + ab), tid);
        __syncthreads();
        if (kt < 23) {
            ldg_w(pw, g_W2h, TXT * 2, (kt + 1) * 32, tid);
            ldg_t(pt, text, row0, (kt + 1) * 32, tid);
        } else {
            ldg_w(pw, g_W3h, 1024, 0, tid);
        }
        kstep2(uA2h + ab,      aMT2, uBh + wb,      acc);
        kstep2(uA2h + ab + 32, aMT2, uBh + wb + 32, acc);
    }
    __syncthreads();
    ln_writeback(acc, vec + V_TB, statS, statQ, A3h, 0, s_at, wm, wn, lane);

    // ---- phase 3: classifier GEMM (K=512, 16 tiles) ----
#pragma unroll
    for (int mt = 0; mt < 2; mt++)
#pragma unroll
        for (int nt = 0; nt < 8; nt++)
#pragma unroll
            for (int j = 0; j < 4; j++) acc[mt][nt][j] = 0.f;

    for (int kt = 0; kt < 16; kt++) {
        const int wb = (kt & 1) * BUF_WB;
        sts_w(pw, (__half*)((char*)Bh + wb), tid);
        __syncthreads();
        if (kt < 15) ldg_w(pw, g_W3h, 1024, (kt + 1) * 32, tid);
        unsigned a3h = uA3h + kt * 64;
        kstep2(a3h,      aMT3, uBh + wb,      acc);
        kstep2(a3h + 32, aMT3, uBh + wb + 32, acc);
    }

    // ---- phase 4: rank-1 corrections, final LN + ReLU + head ----
    const int q = lane & 3, rq = lane >> 2;
    float at4[4], ab4[4];
#pragma unroll
    for (int i = 0; i < 4; i++) {
        int r = wm * 32 + (i >> 1) * 16 + rq + (i & 1) * 8;
        at4[i] = s_at[r];
        ab4[i] = s_ab[r];
    }
#pragma unroll
    for (int mt = 0; mt < 2; mt++)
#pragma unroll
        for (int nt = 0; nt < 8; nt++) {
            int c = wn * 64 + nt * 8 + 2 * q;
#pragma unroll
            for (int d = 0; d < 2; d++) {
                float uA = vec[V_UA + c + d];
                float uB = vec[V_UB + c + d];
                float e  = vec[V_E  + c + d];
#pragma unroll
                for (int h = 0; h < 2; h++) {
                    int i = mt * 2 + h;
                    acc[mt][nt][2 * h + d] =
                        fmaf(at4[i], uA, fmaf(ab4[i], uB, acc[mt][nt][2 * h + d] + e));
                }
            }
        }
    float s4[4], q4[4];
#pragma unroll
    for (int mt = 0; mt < 2; mt++) {
        float s0 = 0, q0 = 0, s1 = 0, q1 = 0;
#pragma unroll
        for (int nt = 0; nt < 8; nt++) {
            s0 += acc[mt][nt][0] + acc[mt][nt][1];
            s1 += acc[mt][nt][2] + acc[mt][nt][3];
            q0 = fmaf(acc[mt][nt][0], acc[mt][nt][0], fmaf(acc[mt][nt][1], acc[mt][nt][1], q0));
            q1 = fmaf(acc[mt][nt][2], acc[mt][nt][2], fmaf(acc[mt][nt][3], acc[mt][nt][3], q1));
        }
        s4[mt * 2] = s0; q4[mt * 2] = q0; s4[mt * 2 + 1] = s1; q4[mt * 2 + 1] = q1;
    }
#pragma unroll
    for (int o = 1; o <= 2; o <<= 1)
#pragma unroll
        for (int i = 0; i < 4; i++) {
            s4[i] += __shfl_xor_sync(0xffffffffu, s4[i], o);
            q4[i] += __shfl_xor_sync(0xffffffffu, q4[i], o);
        }
    __syncthreads();
    if (q == 0) {
#pragma unroll
        for (int i = 0; i < 4; i++) {
            int r = wm * 32 + (i >> 1) * 16 + rq + (i & 1) * 8;
            statS[wn * 128 + r] = s4[i];
            statQ[wn * 128 + r] = q4[i];
        }
    }
    __syncthreads();
    float mm[4], iv4[4];
#pragma unroll
    for (int i = 0; i < 4; i++) {
        int r = wm * 32 + (i >> 1) * 16 + rq + (i & 1) * 8;
        float S = statS[r] + statS[128 + r] + statS[256 + r] + statS[384 + r];
        float Q = statQ[r] + statQ[128 + r] + statQ[256 + r] + statQ[384 + r];
        mm[i]  = S * (1.f / H);
        iv4[i] = rsqrtf(fmaf(Q, 1.f / H, -mm[i] * mm[i]) + EPSLN);
    }
    float p0[4] = {0, 0, 0, 0}, p1[4] = {0, 0, 0, 0};
#pragma unroll
    for (int mt = 0; mt < 2; mt++)
#pragma unroll
        for (int nt = 0; nt < 8; nt++) {
            int c = wn * 64 + nt * 8 + 2 * q;
#pragma unroll
            for (int d = 0; d < 2; d++) {
                float cg = vec[V_CG + c + d], cb = vec[V_CB + c + d];
                float w0 = vec[V_C2 + c + d], w1 = vec[V_C2 + 256 + c + d];
#pragma unroll
                for (int h = 0; h < 2; h++) {
                    int i = mt * 2 + h;
                    float hv = fmaf((acc[mt][nt][2 * h + d] - mm[i]) * iv4[i], cg, cb);
                    hv = fmaxf(hv, 0.f);
                    p0[i] = fmaf(hv, w0, p0[i]);
                    p1[i] = fmaf(hv, w1, p1[i]);
                }
            }
        }
#pragma unroll
    for (int o = 1; o <= 2; o <<= 1)
#pragma unroll
        for (int i = 0; i < 4; i++) {
            p0[i] += __shfl_xor_sync(0xffffffffu, p0[i], o);
            p1[i] += __shfl_xor_sync(0xffffffffu, p1[i], o);
        }
    if (q == 0) {
#pragma unroll
        for (int i = 0; i < 4; i++) {
            int r = wm * 32 + (i >> 1) * 16 + rq + (i & 1) * 8;
            s_hd[wn * 256 + r * 2]     = p0[i];
            s_hd[wn * 256 + r * 2 + 1] = p1[i];
        }
    }
    __syncthreads();
    if (tid < TM) {
        int r = row0 + tid;
        out[2 * r]     = s_hd[tid * 2]       + s_hd[256 + tid * 2] +
                         s_hd[512 + tid * 2] + s_hd[768 + tid * 2] + c2b0;
        out[2 * r + 1] = s_hd[tid * 2 + 1]       + s_hd[256 + tid * 2 + 1] +
                         s_hd[512 + tid * 2 + 1] + s_hd[768 + tid * 2 + 1] + c2b1;
    }
}

// ---------------- launch ----------------
extern "C" void kernel_launch(void* const* d_in, const int* in_sizes, int n_in,
                              void* d_out, int out_size) {
    const float* bio       = (const float*)d_in[0];
    const float* text      = (const float*)d_in[1];
    const float* bio_w     = (const float*)d_in[2];
    const float* bio_b     = (const float*)d_in[3];
    const float* text_w    = (const float*)d_in[4];
    const float* text_b    = (const float*)d_in[5];
    const float* ln_bio_g  = (const float*)d_in[6];
    const float* ln_bio_b  = (const float*)d_in[7];
    const float* ln_text_g = (const float*)d_in[8];
    const float* ln_text_b = (const float*)d_in[9];
    const float* in_proj_w = (const float*)d_in[10];
    const float* in_proj_b = (const float*)d_in[11];
    const float* out_w     = (const float*)d_in[12];
    const float* out_b     = (const float*)d_in[13];
    const float* cls1_w    = (const float*)d_in[14];
    const float* cls1_b    = (const float*)d_in[15];
    const float* cls_ln_g  = (const float*)d_in[16];
    const float* cls_ln_b  = (const float*)d_in[17];
    const float* cls2_w    = (const float*)d_in[18];
    const float* cls2_b    = (const float*)d_in[19];
    float* out = (float*)d_out;

    const int B = in_sizes[0] / BIO;   // 65536

    precompute1<<<H / PRC, 256>>>(in_proj_w, in_proj_b, out_w, out_b);
    precompute2<<<H / PRC, 256>>>(cls1_w, cls1_b, ln_text_g, ln_text_b, ln_bio_g, ln_bio_b);
    convert_weights<<<(H * TXT + 255) / 256, 256>>>(bio_w, text_w);

    cudaFuncSetAttribute(fused_main, cudaFuncAttributeMaxDynamicSharedMemorySize, SMEM_BYTES);
    fused_main<<<B / TM, NTHR, SMEM_BYTES>>>(bio, text, bio_b, text_b,
                                             cls_ln_g, cls_ln_b,
                                             cls2_w, cls2_b, out);
}